// round 15
// baseline (speedup 1.0000x reference)
#include <cuda_runtime.h>
#include <math.h>
#include <cstdint>

#define B_  4
#define L_  1024
#define D_  1024
#define H_  16
#define TWO_PI_F 6.283185307179586f
#define NBLK 256

// ---------------- scratch (device globals; zero-initialized at load) ----------------
__device__ float g_hsum[2 * B_ * D_];  // 2 replicas of per-batch column sums
__device__ float g_vbar[B_ * D_];      // mean-V row per batch (fully overwritten each run)
// Tree-barrier counters (monotonic, never reset -> replay- and interrupt-safe).
// 8 leaves x 8-int padding (32B apart) per barrier + padded root.
__device__ int g_leafA[64];
__device__ int g_rootA[8];
__device__ int g_leafB[64];
__device__ int g_rootB[8];

// Two-level monotonic generation barrier: 32 arrivals per leaf (8 leaves), 8 per root.
// Longest serialized same-address atomic chain = 32 (vs 256 flat).
// Generation g is derived from this block's own leaf arrival index; root target is
// (g+1)*8 on a monotonic counter, so interrupted prior launches can never deadlock us.
__device__ __forceinline__ void grid_barrier(int* leaf_base, int* root) {
    __syncthreads();
    if (threadIdx.x == 0) {
        __threadfence();
        int* leaf = leaf_base + (blockIdx.x & 7) * 8;
        int a = atomicAdd(leaf, 1);
        int g = a >> 5;                      // 32 arrivals per leaf per instance
        if ((a & 31) == 31) atomicAdd(root, 1);
        int target = (g + 1) * 8;
        while (*(volatile int*)root < target) __nanosleep(20);
        __threadfence();
    }
    __syncthreads();
}

__device__ __forceinline__ float4 ldcs4(const float* p) {
    return __ldcs((const float4*)p);
}
__device__ __forceinline__ void stcs4(float* p, float4 v) {
    __stcs((float4*)p, v);
}
__device__ __forceinline__ uint32_t smem_u32(const void* p) {
    uint32_t a;
    asm("{ .reg .u64 t; cvta.to.shared.u64 t, %1; cvt.u32.u64 %0, t; }" : "=r"(a) : "l"(p));
    return a;
}
__device__ __forceinline__ void cp_async16(uint32_t dst, const void* src) {
    asm volatile("cp.async.cg.shared.global [%0], [%1], 16;" :: "r"(dst), "l"(src) : "memory");
}
#define CP_ASYNC_COMMIT() asm volatile("cp.async.commit_group;" ::: "memory")
#define CP_ASYNC_WAIT0()  asm volatile("cp.async.wait_group 0;" ::: "memory")

// ================= single fused kernel =================
// 256 blocks x 256 threads, all co-resident in one wave.
// Entry: cp.async this block's 8 Wv rows (32 KB) into smem  — overlaps Stage A.
// Stage A: per-batch column sums of hidden (block = (b, 16-row slab); atomics into
//          replica bid&1 — halves per-address atomic chains), then L2-prefetch a
//          distinct 16 KB Wo slice (256 blocks cover Wo exactly).
// Tree barrier.  Stage B: vbar = (rep0+rep1) @ Wv^T / L + bv (warp per (col, batch-pair)).
// Tree barrier.  Stage C: orow = vbar @ Wo^T + bo, broadcast (block = (b, 32-col, row-half)).
// Stage P (block 0, LAST): Kuramoto phases — off the critical path.
__global__ __launch_bounds__(256) void fused_kernel(
    const float* __restrict__ hs,  const float* __restrict__ Wv,
    const float* __restrict__ bv,  const float* __restrict__ Wo,
    const float* __restrict__ bo,  const float* __restrict__ base,
    const float* __restrict__ natf, const float* __restrict__ phs,
    float* __restrict__ out)
{
    __shared__ float wv_s[8 * D_];   // this block's 8 Wv rows (32 KB)
    __shared__ float xs[D_];
    __shared__ float os[32];
    __shared__ float ph_s[H_];

    const int tid = threadIdx.x, bid = blockIdx.x;
    float* hsum = g_hsum;                      // [2][B_*D_]
    float* vbar = g_vbar;
    float* out_phases = out + (size_t)B_ * L_ * D_;
    float* out_order  = out_phases + B_ * H_;

    // ---- entry: stage Wv rows for Stage B into smem (in flight during Stage A) ----
    {
        const float* wsrc = Wv + (size_t)((bid & 127) * 8) * D_;
        const uint32_t wdst = smem_u32(wv_s);
#pragma unroll
        for (int v = 0; v < 8; v++) {
            int idx = v * 256 + tid;                 // 2048 x 16B = 32 KB
            cp_async16(wdst + idx * 16, wsrc + idx * 4);
        }
        CP_ASYNC_COMMIT();
    }

    // ---- Stage A: column sums (block = (b, 16-row slab); replica = bid&1) ----
    {
        const int b  = bid >> 6;
        const int l0 = (bid & 63) * 16;
        const int d  = tid * 4;
        const float* src = hs + ((size_t)b * L_ + l0) * D_ + d;
        float4 acc = make_float4(0.f, 0.f, 0.f, 0.f);
#pragma unroll
        for (int r = 0; r < 16; r++) {
            float4 v = ldcs4(src + (size_t)r * D_);
            acc.x += v.x; acc.y += v.y; acc.z += v.z; acc.w += v.w;
        }
        float* dst = hsum + (bid & 1) * (B_ * D_) + b * D_ + d;
        atomicAdd(dst + 0, acc.x);
        atomicAdd(dst + 1, acc.y);
        atomicAdd(dst + 2, acc.z);
        atomicAdd(dst + 3, acc.w);
    }

    // ---- L2 prefetch of Wo (each block a distinct 16 KB slice; 256 x 16 KB = 4 MB) ----
    if (tid < 128) {
        const float* wop = Wo + (size_t)bid * 4096 + tid * 32;   // 128B line per thread
        asm volatile("prefetch.global.L2 [%0];" :: "l"(wop));
    }

    grid_barrier(g_leafA, g_rootA);

    // ---- Stage B: vbar = (rep0+rep1) @ Wv^T / L + bv (warp per (col, batch-pair)) ----
    {
        CP_ASYNC_WAIT0();
        __syncthreads();
        const int wid = tid >> 5, lane = tid & 31;
        const int n  = (bid & 127) * 8 + wid;
        const int bp = (bid >> 7) * 2;           // batches bp, bp+1
        const float* wr = wv_s + wid * D_;
        float a0 = 0.f, a1 = 0.f;
#pragma unroll
        for (int it = 0; it < 8; it++) {
            int k = it * 128 + lane * 4;
            float4 wv = *(const float4*)(wr + k);
            float4 p0 = __ldcg((const float4*)(hsum + (bp + 0) * D_ + k));
            float4 q0 = __ldcg((const float4*)(hsum + B_ * D_ + (bp + 0) * D_ + k));
            float4 p1 = __ldcg((const float4*)(hsum + (bp + 1) * D_ + k));
            float4 q1 = __ldcg((const float4*)(hsum + B_ * D_ + (bp + 1) * D_ + k));
            float4 x0 = make_float4(p0.x + q0.x, p0.y + q0.y, p0.z + q0.z, p0.w + q0.w);
            float4 x1 = make_float4(p1.x + q1.x, p1.y + q1.y, p1.z + q1.z, p1.w + q1.w);
            a0 = fmaf(x0.x, wv.x, fmaf(x0.y, wv.y, fmaf(x0.z, wv.z, fmaf(x0.w, wv.w, a0))));
            a1 = fmaf(x1.x, wv.x, fmaf(x1.y, wv.y, fmaf(x1.z, wv.z, fmaf(x1.w, wv.w, a1))));
        }
#pragma unroll
        for (int o = 16; o > 0; o >>= 1) {
            a0 += __shfl_xor_sync(0xffffffffu, a0, o);
            a1 += __shfl_xor_sync(0xffffffffu, a1, o);
        }
        if (lane == 0) {
            const float bias = bv[n];
            const float inv = 1.0f / (float)L_;
            vbar[(bp + 0) * D_ + n] = a0 * inv + bias;
            vbar[(bp + 1) * D_ + n] = a1 * inv + bias;
        }
    }

    grid_barrier(g_leafB, g_rootB);

    // re-zero this block's slice of both hsum replicas (dead after Stage B)
    if (tid < 32) hsum[bid * 32 + tid] = 0.f;     // 256*32 = 8192 = 2*B_*D_

    // ---- Stage C: orow = vbar @ Wo^T + bo, broadcast ----
    // block = (b = bid>>6, n0 = ((bid>>1)&31)*32, row-half = bid&1)
    {
        const int b  = bid >> 6;
        const int n0 = ((bid >> 1) & 31) * 32;
        const int l0 = (bid & 1) * 512;

        *(float4*)&xs[tid * 4] = __ldcg((const float4*)(vbar + b * D_ + tid * 4));
        __syncthreads();

        const int wid = tid >> 5, lane = tid & 31;
#pragma unroll
        for (int i = 0; i < 4; i++) {
            const int nn = wid * 4 + i;
            const float* wr = Wo + (size_t)(n0 + nn) * D_;
            float a = 0.f;
#pragma unroll
            for (int it = 0; it < 8; it++) {
                int k = it * 128 + lane * 4;
                float4 wv = *(const float4*)(wr + k);
                float4 xv = *(const float4*)&xs[k];
                a = fmaf(xv.x, wv.x, fmaf(xv.y, wv.y, fmaf(xv.z, wv.z, fmaf(xv.w, wv.w, a))));
            }
#pragma unroll
            for (int o = 16; o > 0; o >>= 1) a += __shfl_xor_sync(0xffffffffu, a, o);
            if (lane == 0) os[nn] = a + bo[n0 + nn];
        }
        __syncthreads();

        // each thread owns one 16-B segment value; one aligned 128-B line per row-write
        const int seg = tid & 7;
        const float4 v = ((const float4*)os)[seg];
        float* obase = out + (size_t)b * L_ * D_ + n0 + seg * 4;
#pragma unroll 8
        for (int i = tid; i < 4096; i += 256) {
            int l = l0 + (i >> 3);
            stcs4(obase + (size_t)l * D_, v);
        }
    }

    // ---- Stage P: phases (block 0, LAST — off the critical path) ----
    if (bid == 0) {
        const int h = tid >> 4, j = tid & 15;
        {
            const float th = phs[h], tj = phs[j];
            float v = base[h * H_ + j];
            float mx = v;
#pragma unroll
            for (int o = 1; o < 16; o <<= 1) mx = fmaxf(mx, __shfl_xor_sync(0xffffffffu, mx, o));
            float e = __expf(v - mx);
            float s = e;
#pragma unroll
            for (int o = 1; o < 16; o <<= 1) s += __shfl_xor_sync(0xffffffffu, s, o);
            float term = (e / s) * __sinf(th - tj);
#pragma unroll
            for (int o = 1; o < 16; o <<= 1) term += __shfl_xor_sync(0xffffffffu, term, o);
            if (j == 0) {
                float dph = natf[h] + term / (float)H_;
                ph_s[h] = fmodf(th + 0.1f * dph, TWO_PI_F);
            }
        }
        __syncthreads();
        if (tid < H_) {
            float p = ph_s[tid];
            float c = __cosf(p), si = __sinf(p);
#pragma unroll
            for (int o = 8; o > 0; o >>= 1) {
                c  += __shfl_xor_sync(0x0000ffffu, c,  o);
                si += __shfl_xor_sync(0x0000ffffu, si, o);
            }
            c /= (float)H_; si /= (float)H_;
            float order = sqrtf(c * c + si * si);
#pragma unroll
            for (int b = 0; b < B_; b++) out_phases[b * H_ + tid] = p;
            if (tid == 0)
#pragma unroll
                for (int b = 0; b < B_; b++) out_order[b] = order;
        }
    }
}

// ================= launch =================
extern "C" void kernel_launch(void* const* d_in, const int* in_sizes, int n_in,
                              void* d_out, int out_size)
{
    const float* hs   = (const float*)d_in[0];
    // d_in[1..4] (Wq,bq,Wk,bk) provably do not affect the output at fp32 precision
    const float* Wv   = (const float*)d_in[5];
    const float* bv   = (const float*)d_in[6];
    const float* Wo   = (const float*)d_in[7];
    const float* bo   = (const float*)d_in[8];
    const float* base = (const float*)d_in[9];
    const float* natf = (const float*)d_in[10];
    const float* phs  = (const float*)d_in[11];
    float* out = (float*)d_out;

    fused_kernel<<<NBLK, 256>>>(hs, Wv, bv, Wo, bo, base, natf, phs, out);
}

// round 16
// speedup vs baseline: 1.0311x; 1.0311x over previous
#include <cuda_runtime.h>
#include <math.h>
#include <cstdint>

#define B_  4
#define L_  1024
#define D_  1024
#define H_  16
#define TWO_PI_F 6.283185307179586f
#define NBLK 256
#define GBLK 64          // blocks per batch-group

// ---------------- scratch (device globals; zero-initialized at load) ----------------
__device__ float g_hsum[B_ * D_];   // per-batch column sums (re-zeroed in dead window)
__device__ float g_vbar[B_ * D_];   // mean-V row per batch (fully overwritten each run)
__device__ int   g_ctrA[32];        // per-group barrier counters (g*8), monotonic
__device__ int   g_ctrB[32];

// Per-group monotonic generation barrier: 64 arrivals, replay/interrupt-safe
// (counters never reset; replays are stream-serialized).
__device__ __forceinline__ void group_barrier(int* ctr) {
    __syncthreads();
    if (threadIdx.x == 0) {
        __threadfence();
        int arrival = atomicAdd(ctr, 1);
        int target  = (arrival / GBLK + 1) * GBLK;
        while (*(volatile int*)ctr < target) __nanosleep(20);
        __threadfence();
    }
    __syncthreads();
}

__device__ __forceinline__ float4 ldcs4(const float* p) {
    return __ldcs((const float4*)p);
}
__device__ __forceinline__ void stcs4(float* p, float4 v) {
    __stcs((float4*)p, v);
}

// ================= single fused kernel, per-batch pipelined =================
// 256 blocks = 4 independent groups of 64 (group g = batch). Each group runs
// A -> barrier_g -> B -> barrier_g -> C privately; natural skew between groups
// overlaps group X's 4 MB read stream with group Y's 4 MB write stream.
// Stage A: column sums of hidden[b] (block r: 16-row slab; atomics).
// Stage B: vbar[b, r*16..r*16+16) = hsum[b] @ Wv^T / L + bv  (2 cols per warp).
// Stage C: orow[b, n0..n0+32) = vbar[b] @ Wo^T + bo, broadcast to 512 rows.
// Stage P (block 0, LAST): Kuramoto phases — off the critical path.
__global__ __launch_bounds__(256) void fused_kernel(
    const float* __restrict__ hs,  const float* __restrict__ Wv,
    const float* __restrict__ bv,  const float* __restrict__ Wo,
    const float* __restrict__ bo,  const float* __restrict__ base,
    const float* __restrict__ natf, const float* __restrict__ phs,
    float* __restrict__ out)
{
    __shared__ float xs[D_];
    __shared__ float os[32];
    __shared__ float ph_s[H_];

    const int tid = threadIdx.x, bid = blockIdx.x;
    const int g = bid >> 6;          // batch / group
    const int r = bid & 63;          // rank within group
    float* hsum = g_hsum;
    float* vbar = g_vbar;
    float* out_phases = out + (size_t)B_ * L_ * D_;
    float* out_order  = out_phases + B_ * H_;

    // ---- Stage A: column sums (block r: rows r*16 .. r*16+16 of batch g) ----
    {
        const int l0 = r * 16;
        const int d  = tid * 4;
        const float* src = hs + ((size_t)g * L_ + l0) * D_ + d;
        float4 acc = make_float4(0.f, 0.f, 0.f, 0.f);
#pragma unroll
        for (int rr = 0; rr < 16; rr++) {
            float4 v = ldcs4(src + (size_t)rr * D_);
            acc.x += v.x; acc.y += v.y; acc.z += v.z; acc.w += v.w;
        }
        float* dst = hsum + g * D_ + d;
        atomicAdd(dst + 0, acc.x);
        atomicAdd(dst + 1, acc.y);
        atomicAdd(dst + 2, acc.z);
        atomicAdd(dst + 3, acc.w);
    }

    group_barrier(&g_ctrA[g * 8]);

    // ---- Stage B: vbar[g, r*16 .. r*16+16) (warp -> 2 cols) ----
    {
        const int wid = tid >> 5, lane = tid & 31;
        const int n = r * 16 + wid * 2;
        const float* w0 = Wv + (size_t)n * D_;
        const float* w1 = Wv + (size_t)(n + 1) * D_;
        const float* xr = hsum + g * D_;
        float a0 = 0.f, a1 = 0.f;
#pragma unroll
        for (int it = 0; it < 8; it++) {
            int k = it * 128 + lane * 4;
            float4 xv = __ldcg((const float4*)(xr + k));
            float4 v0 = *(const float4*)(w0 + k);
            float4 v1 = *(const float4*)(w1 + k);
            a0 = fmaf(xv.x, v0.x, fmaf(xv.y, v0.y, fmaf(xv.z, v0.z, fmaf(xv.w, v0.w, a0))));
            a1 = fmaf(xv.x, v1.x, fmaf(xv.y, v1.y, fmaf(xv.z, v1.z, fmaf(xv.w, v1.w, a1))));
        }
#pragma unroll
        for (int o = 16; o > 0; o >>= 1) {
            a0 += __shfl_xor_sync(0xffffffffu, a0, o);
            a1 += __shfl_xor_sync(0xffffffffu, a1, o);
        }
        if (lane == 0) {
            const float inv = 1.0f / (float)L_;
            vbar[g * D_ + n]     = a0 * inv + bv[n];
            vbar[g * D_ + n + 1] = a1 * inv + bv[n + 1];
        }
    }

    group_barrier(&g_ctrB[g * 8]);

    // re-zero this block's hsum slice (dead after Stage B) for the next replay
    if (tid < 16) hsum[g * D_ + r * 16 + tid] = 0.f;

    // ---- Stage C: orow[g, n0..n0+32), broadcast to rows l0..l0+512 ----
    // r -> (n0 = (r>>1)*32, row-half = r&1)
    {
        const int n0 = (r >> 1) * 32;
        const int l0 = (r & 1) * 512;

        *(float4*)&xs[tid * 4] = __ldcg((const float4*)(vbar + g * D_ + tid * 4));
        __syncthreads();

        const int wid = tid >> 5, lane = tid & 31;
#pragma unroll
        for (int i = 0; i < 4; i++) {
            const int nn = wid * 4 + i;
            const float* wr = Wo + (size_t)(n0 + nn) * D_;
            float a = 0.f;
#pragma unroll
            for (int it = 0; it < 8; it++) {
                int k = it * 128 + lane * 4;
                float4 wv = *(const float4*)(wr + k);
                float4 xv = *(const float4*)&xs[k];
                a = fmaf(xv.x, wv.x, fmaf(xv.y, wv.y, fmaf(xv.z, wv.z, fmaf(xv.w, wv.w, a))));
            }
#pragma unroll
            for (int o = 16; o > 0; o >>= 1) a += __shfl_xor_sync(0xffffffffu, a, o);
            if (lane == 0) os[nn] = a + bo[n0 + nn];
        }
        __syncthreads();

        // each thread owns one 16-B segment value; one aligned 128-B line per row-write
        const int seg = tid & 7;
        const float4 v = ((const float4*)os)[seg];
        float* obase = out + (size_t)g * L_ * D_ + n0 + seg * 4;
#pragma unroll 8
        for (int i = tid; i < 4096; i += 256) {
            int l = l0 + (i >> 3);
            stcs4(obase + (size_t)l * D_, v);
        }
    }

    // ---- Stage P: phases (block 0, LAST — off the critical path) ----
    if (bid == 0) {
        const int h = tid >> 4, j = tid & 15;
        {
            const float th = phs[h], tj = phs[j];
            float v = base[h * H_ + j];
            float mx = v;
#pragma unroll
            for (int o = 1; o < 16; o <<= 1) mx = fmaxf(mx, __shfl_xor_sync(0xffffffffu, mx, o));
            float e = __expf(v - mx);
            float s = e;
#pragma unroll
            for (int o = 1; o < 16; o <<= 1) s += __shfl_xor_sync(0xffffffffu, s, o);
            float term = (e / s) * __sinf(th - tj);
#pragma unroll
            for (int o = 1; o < 16; o <<= 1) term += __shfl_xor_sync(0xffffffffu, term, o);
            if (j == 0) {
                float dph = natf[h] + term / (float)H_;
                ph_s[h] = fmodf(th + 0.1f * dph, TWO_PI_F);
            }
        }
        __syncthreads();
        if (tid < H_) {
            float p = ph_s[tid];
            float c = __cosf(p), si = __sinf(p);
#pragma unroll
            for (int o = 8; o > 0; o >>= 1) {
                c  += __shfl_xor_sync(0x0000ffffu, c,  o);
                si += __shfl_xor_sync(0x0000ffffu, si, o);
            }
            c /= (float)H_; si /= (float)H_;
            float order = sqrtf(c * c + si * si);
#pragma unroll
            for (int b = 0; b < B_; b++) out_phases[b * H_ + tid] = p;
            if (tid == 0)
#pragma unroll
                for (int b = 0; b < B_; b++) out_order[b] = order;
        }
    }
}

// ================= launch =================
extern "C" void kernel_launch(void* const* d_in, const int* in_sizes, int n_in,
                              void* d_out, int out_size)
{
    const float* hs   = (const float*)d_in[0];
    // d_in[1..4] (Wq,bq,Wk,bk) provably do not affect the output at fp32 precision
    const float* Wv   = (const float*)d_in[5];
    const float* bv   = (const float*)d_in[6];
    const float* Wo   = (const float*)d_in[7];
    const float* bo   = (const float*)d_in[8];
    const float* base = (const float*)d_in[9];
    const float* natf = (const float*)d_in[10];
    const float* phs  = (const float*)d_in[11];
    float* out = (float*)d_out;

    fused_kernel<<<NBLK, 256>>>(hs, Wv, bv, Wo, bo, base, natf, phs, out);
}

// round 17
// speedup vs baseline: 1.1411x; 1.1067x over previous
#include <cuda_runtime.h>
#include <math.h>
#include <cstdint>

#define B_  4
#define L_  1024
#define D_  1024
#define H_  16
#define TWO_PI_F 6.283185307179586f
#define NBLK 128

// ---------------- scratch (device globals; zero-initialized at load) ----------------
__device__ float g_hsum[B_ * D_];   // per-batch column sums (re-zeroed in dead window)
__device__ float g_vbar[B_ * D_];   // mean-V row per batch (fully overwritten each run)
__device__ int   g_ctr[64];         // monotonic barrier counters at [0] and [32]

// Monotonic generation grid-barrier (flat, 128 arrivals): replay/interrupt-safe.
__device__ __forceinline__ void grid_barrier(int* ctr) {
    __syncthreads();
    if (threadIdx.x == 0) {
        __threadfence();
        int arrival = atomicAdd(ctr, 1);
        int target  = (arrival / NBLK + 1) * NBLK;
        while (*(volatile int*)ctr < target) __nanosleep(20);
        __threadfence();
    }
    __syncthreads();
}

__device__ __forceinline__ float4 ldcs4(const float* p) {
    return __ldcs((const float4*)p);
}
__device__ __forceinline__ void stcs4(float* p, float4 v) {
    __stcs((float4*)p, v);
}

// ================= single fused kernel: 128 blocks x 1024 threads =================
// 2 blocks/SM co-resident -> ~64 warps/SM during every stage (full occupancy for the
// memory streams) while the grid barrier has only 128 arrivals.
// Stage A: block (b = bid>>5, 32-row slab): 4 row-groups reduce in smem, then one
//          scalar atomicAdd per column per block (32-deep per-address chains).
// Barrier.  Stage B: warp w -> col (bid&31)*32+w of batch bid>>5 (4096 warp-tasks).
// Barrier.  Stage C: block (b, 32-col chunk): 32 warp-dots vs smem vbar, broadcast
//           to ALL 1024 rows (8 full-line stores per thread).
// Stage P (block 0, LAST): Kuramoto phases — off the critical path.
__global__ __launch_bounds__(1024) void fused_kernel(
    const float* __restrict__ hs,  const float* __restrict__ Wv,
    const float* __restrict__ bv,  const float* __restrict__ Wo,
    const float* __restrict__ bo,  const float* __restrict__ base,
    const float* __restrict__ natf, const float* __restrict__ phs,
    float* __restrict__ out)
{
    __shared__ float red[4 * D_];    // Stage A row-group partials (16 KB)
    __shared__ float xs[D_];         // Stage C vbar row (4 KB)
    __shared__ float os[32];
    __shared__ float ph_s[H_];

    const int tid = threadIdx.x, bid = blockIdx.x;
    const int b  = bid >> 5;               // batch (Stages A and C)
    const int c32 = bid & 31;              // 32-wide chunk index
    float* hsum = g_hsum;
    float* vbar = g_vbar;
    float* out_phases = out + (size_t)B_ * L_ * D_;
    float* out_order  = out_phases + B_ * H_;

    // ---- Stage A: column sums over 32 rows, smem-reduced, one atomic/column ----
    {
        const int l0  = c32 * 32;
        const int col = (tid & 255) * 4;       // float4 column segment
        const int rg  = tid >> 8;              // row group 0..3 (8 rows each)
        const float* src = hs + ((size_t)b * L_ + l0 + rg * 8) * D_ + col;
        float4 acc = make_float4(0.f, 0.f, 0.f, 0.f);
#pragma unroll
        for (int r = 0; r < 8; r++) {
            float4 v = ldcs4(src + (size_t)r * D_);
            acc.x += v.x; acc.y += v.y; acc.z += v.z; acc.w += v.w;
        }
        *(float4*)&red[rg * D_ + col] = acc;
        __syncthreads();
        // 1024 threads: thread t sums the 4 row-group partials of column t
        float s = red[tid] + red[D_ + tid] + red[2 * D_ + tid] + red[3 * D_ + tid];
        atomicAdd(hsum + b * D_ + tid, s);
    }

    grid_barrier(&g_ctr[0]);

    // ---- Stage B: warp w -> vbar[b, c32*32 + w] ----
    {
        const int wid = tid >> 5, lane = tid & 31;
        const int n = c32 * 32 + wid;
        const float* wr = Wv + (size_t)n * D_;
        const float* xr = hsum + b * D_;
        float a = 0.f;
#pragma unroll
        for (int it = 0; it < 8; it++) {
            int k = it * 128 + lane * 4;
            float4 wv = *(const float4*)(wr + k);
            float4 xv = __ldcg((const float4*)(xr + k));
            a = fmaf(xv.x, wv.x, fmaf(xv.y, wv.y, fmaf(xv.z, wv.z, fmaf(xv.w, wv.w, a))));
        }
#pragma unroll
        for (int o = 16; o > 0; o >>= 1) a += __shfl_xor_sync(0xffffffffu, a, o);
        if (lane == 0)
            vbar[b * D_ + n] = a * (1.0f / (float)L_) + bv[n];
    }

    grid_barrier(&g_ctr[32]);

    // re-zero this block's hsum slice (dead after Stage B) for the next replay
    if (tid < 32) hsum[bid * 32 + tid] = 0.f;   // 128*32 = 4096 = B_*D_

    // ---- Stage C: orow[b, c32*32 .. +32), broadcast to all 1024 rows ----
    {
        const int n0 = c32 * 32;

        if (tid < 256)
            *(float4*)&xs[tid * 4] = __ldcg((const float4*)(vbar + b * D_ + tid * 4));
        __syncthreads();

        const int wid = tid >> 5, lane = tid & 31;
        {
            const int nn = wid;                      // warp per column
            const float* wr = Wo + (size_t)(n0 + nn) * D_;
            float a = 0.f;
#pragma unroll
            for (int it = 0; it < 8; it++) {
                int k = it * 128 + lane * 4;
                float4 wv = *(const float4*)(wr + k);
                float4 xv = *(const float4*)&xs[k];
                a = fmaf(xv.x, wv.x, fmaf(xv.y, wv.y, fmaf(xv.z, wv.z, fmaf(xv.w, wv.w, a))));
            }
#pragma unroll
            for (int o = 16; o > 0; o >>= 1) a += __shfl_xor_sync(0xffffffffu, a, o);
            if (lane == 0) os[nn] = a + bo[n0 + nn];
        }
        __syncthreads();

        // broadcast: seg = tid&7 (16-B segment), rows l = i>>3; 8 stores/thread,
        // each store one aligned 128-B line segment
        const int seg = tid & 7;
        const float4 v = ((const float4*)os)[seg];
        float* obase = out + (size_t)b * L_ * D_ + n0 + seg * 4;
#pragma unroll 8
        for (int i = tid; i < 8192; i += 1024) {
            int l = i >> 3;
            stcs4(obase + (size_t)l * D_, v);
        }
    }

    // ---- Stage P: phases (block 0, LAST — off the critical path) ----
    if (bid == 0 && tid < 256) {
        const int h = tid >> 4, j = tid & 15;
        {
            const float th = phs[h], tj = phs[j];
            float v = base[h * H_ + j];
            float mx = v;
#pragma unroll
            for (int o = 1; o < 16; o <<= 1) mx = fmaxf(mx, __shfl_xor_sync(0xffffffffu, mx, o));
            float e = __expf(v - mx);
            float s = e;
#pragma unroll
            for (int o = 1; o < 16; o <<= 1) s += __shfl_xor_sync(0xffffffffu, s, o);
            float term = (e / s) * __sinf(th - tj);
#pragma unroll
            for (int o = 1; o < 16; o <<= 1) term += __shfl_xor_sync(0xffffffffu, term, o);
            if (j == 0) {
                float dph = natf[h] + term / (float)H_;
                ph_s[h] = fmodf(th + 0.1f * dph, TWO_PI_F);
            }
            __syncwarp();
        }
        if (h == 0) {   // lanes 0..15 of warp 0 finish (ph_s written by warps 0..15's lane groups)
        }
    }
    if (bid == 0) {
        __syncthreads();
        if (tid < H_) {
            float p = ph_s[tid];
            float c = __cosf(p), si = __sinf(p);
#pragma unroll
            for (int o = 8; o > 0; o >>= 1) {
                c  += __shfl_xor_sync(0x0000ffffu, c,  o);
                si += __shfl_xor_sync(0x0000ffffu, si, o);
            }
            c /= (float)H_; si /= (float)H_;
            float order = sqrtf(c * c + si * si);
#pragma unroll
            for (int bb = 0; bb < B_; bb++) out_phases[bb * H_ + tid] = p;
            if (tid == 0)
#pragma unroll
                for (int bb = 0; bb < B_; bb++) out_order[bb] = order;
        }
    }
}

// ================= launch =================
extern "C" void kernel_launch(void* const* d_in, const int* in_sizes, int n_in,
                              void* d_out, int out_size)
{
    const float* hs   = (const float*)d_in[0];
    // d_in[1..4] (Wq,bq,Wk,bk) provably do not affect the output at fp32 precision
    const float* Wv   = (const float*)d_in[5];
    const float* bv   = (const float*)d_in[6];
    const float* Wo   = (const float*)d_in[7];
    const float* bo   = (const float*)d_in[8];
    const float* base = (const float*)d_in[9];
    const float* natf = (const float*)d_in[10];
    const float* phs  = (const float*)d_in[11];
    float* out = (float*)d_out;

    fused_kernel<<<NBLK, 1024>>>(hs, Wv, bv, Wo, bo, base, natf, phs, out);
}